// round 2
// baseline (speedup 1.0000x reference)
#include <cuda_runtime.h>
#include <cstdint>

// Problem constants (from reference)
#define F 8
#define B 4096
#define V 100000
#define D 128
#define NVALS 81920

// One warp per (feature, bag). Lane l owns output floats [4l, 4l+4).
// Table rows are 512B; a warp's float4 loads cover the row fully coalesced.
// 8x unroll => 8 independent LDG.128 in flight per lane (attack latency).
// Table loads use __ldcg (L2-only): random rows never hit L1, don't thrash it.
__global__ __launch_bounds__(256)
void ebc_pooled_kernel(const int* __restrict__ values,    // [F, NVALS]
                       const int* __restrict__ offsets,   // [F, B+1]
                       const float* __restrict__ tables,  // [F, V, D]
                       float* __restrict__ out)           // [B, F*D]
{
    const int gwarp = (blockIdx.x * blockDim.x + threadIdx.x) >> 5;
    const int lane  = threadIdx.x & 31;
    if (gwarp >= F * B) return;

    // f-major: consecutive warps share a table -> table stays hot in L2
    const int f = gwarp >> 12;          // gwarp / B
    const int b = gwarp & (B - 1);      // gwarp % B

    const int start = __ldg(offsets + f * (B + 1) + b);
    const int end   = __ldg(offsets + f * (B + 1) + b + 1);

    const int*    vals = values + (size_t)f * NVALS;
    const float4* tab  = reinterpret_cast<const float4*>(tables + (size_t)f * V * D) + lane;
    const int RS4 = D / 4;  // 32 float4 per row

    float4 acc = make_float4(0.f, 0.f, 0.f, 0.f);

    int i = start;
    // 8x unroll: 8 independent row gathers in flight per lane
    for (; i + 8 <= end; i += 8) {
        const int i0 = __ldg(vals + i + 0);
        const int i1 = __ldg(vals + i + 1);
        const int i2 = __ldg(vals + i + 2);
        const int i3 = __ldg(vals + i + 3);
        const int i4 = __ldg(vals + i + 4);
        const int i5 = __ldg(vals + i + 5);
        const int i6 = __ldg(vals + i + 6);
        const int i7 = __ldg(vals + i + 7);
        const float4 v0 = __ldcg(tab + (size_t)i0 * RS4);
        const float4 v1 = __ldcg(tab + (size_t)i1 * RS4);
        const float4 v2 = __ldcg(tab + (size_t)i2 * RS4);
        const float4 v3 = __ldcg(tab + (size_t)i3 * RS4);
        const float4 v4 = __ldcg(tab + (size_t)i4 * RS4);
        const float4 v5 = __ldcg(tab + (size_t)i5 * RS4);
        const float4 v6 = __ldcg(tab + (size_t)i6 * RS4);
        const float4 v7 = __ldcg(tab + (size_t)i7 * RS4);
        acc.x += (v0.x + v1.x) + (v2.x + v3.x) + (v4.x + v5.x) + (v6.x + v7.x);
        acc.y += (v0.y + v1.y) + (v2.y + v3.y) + (v4.y + v5.y) + (v6.y + v7.y);
        acc.z += (v0.z + v1.z) + (v2.z + v3.z) + (v4.z + v5.z) + (v6.z + v7.z);
        acc.w += (v0.w + v1.w) + (v2.w + v3.w) + (v4.w + v5.w) + (v6.w + v7.w);
    }
    // 2x unroll remainder
    for (; i + 2 <= end; i += 2) {
        const int i0 = __ldg(vals + i + 0);
        const int i1 = __ldg(vals + i + 1);
        const float4 v0 = __ldcg(tab + (size_t)i0 * RS4);
        const float4 v1 = __ldcg(tab + (size_t)i1 * RS4);
        acc.x += v0.x + v1.x;
        acc.y += v0.y + v1.y;
        acc.z += v0.z + v1.z;
        acc.w += v0.w + v1.w;
    }
    if (i < end) {
        const int i0 = __ldg(vals + i);
        const float4 v0 = __ldcg(tab + (size_t)i0 * RS4);
        acc.x += v0.x; acc.y += v0.y; acc.z += v0.z; acc.w += v0.w;
    }

    // out[b, f*D + lane*4 .. +4)
    float4* out4 = reinterpret_cast<float4*>(out);
    out4[(size_t)b * (F * D / 4) + f * RS4 + lane] = acc;
}

extern "C" void kernel_launch(void* const* d_in, const int* in_sizes, int n_in,
                              void* d_out, int out_size)
{
    const int*   values  = (const int*)d_in[0];   // [F, NVALS] int32
    const int*   offsets = (const int*)d_in[1];   // [F, B+1] int32
    const float* tables  = (const float*)d_in[2]; // [F, V, D] float32
    float*       out     = (float*)d_out;         // [B, F*D] float32

    const int total_warps = F * B;                 // 32768
    const int threads = 256;                       // 8 warps/block
    const int blocks = (total_warps * 32) / threads;  // 4096

    ebc_pooled_kernel<<<blocks, threads>>>(values, offsets, tables, out);
}

// round 3
// speedup vs baseline: 1.5776x; 1.5776x over previous
#include <cuda_runtime.h>
#include <cstdint>

// Problem constants (from reference)
#define F 8
#define B 4096
#define V 100000
#define D 128
#define NVALS 81920
#define CHUNK 32
#define CPF (NVALS / CHUNK)   // 2560 chunks per feature

__global__ __launch_bounds__(256)
void zero_out_kernel(float4* __restrict__ out, int n4)
{
    int i = blockIdx.x * blockDim.x + threadIdx.x;
    if (i < n4) out[i] = make_float4(0.f, 0.f, 0.f, 0.f);
}

// One warp per 32-value chunk: perfectly balanced work decomposition.
// Lane l owns float4 slice [4l, 4l+4) of D=128. Partial bag sums are flushed
// to the output with atomicAdd (REDG) at segment boundaries.
__global__ __launch_bounds__(256, 4)   // cap 4 blocks/SM -> 64-reg budget, keeps 8 loads in flight
void ebc_chunk_kernel(const int* __restrict__ values,    // [F, NVALS]
                      const int* __restrict__ offsets,   // [F, B+1]
                      const float* __restrict__ tables,  // [F, V, D]
                      float* __restrict__ out)           // [B, F*D]
{
    const int gwarp = (blockIdx.x * blockDim.x + threadIdx.x) >> 5;
    const int lane  = threadIdx.x & 31;

    // f-major: consecutive warps share a table (L2 locality)
    const int f = gwarp / CPF;
    const int c = gwarp - f * CPF;
    const int pos = c * CHUNK + lane;        // this lane's value position

    const int myidx = __ldg(values + (size_t)f * NVALS + pos);

    // bag id = largest j in [0, B-1] with offs[j] <= pos  (== searchsorted right - 1)
    const int* offs = offsets + f * (B + 1);
    int lo = 0, hi = B - 1;
    #pragma unroll
    for (int it = 0; it < 12; ++it) {        // 2^12 = 4096 covers [0, B-1]
        int mid = (lo + hi + 1) >> 1;
        if (__ldg(offs + mid) <= pos) lo = mid; else hi = mid - 1;
    }
    const int myseg = lo;

    const float4* tab = reinterpret_cast<const float4*>(tables)
                        + (size_t)f * V * (D / 4) + lane;

    float4 acc = make_float4(0.f, 0.f, 0.f, 0.f);
    int cur = __shfl_sync(0xffffffffu, myseg, 0);

    #pragma unroll
    for (int jb = 0; jb < CHUNK / 8; ++jb) {
        // Stage 8 independent warp-wide row gathers (true MLP=8)
        float4 v[8];
        #pragma unroll
        for (int k = 0; k < 8; ++k) {
            const int row = __shfl_sync(0xffffffffu, myidx, jb * 8 + k);
            v[k] = __ldcg(tab + (size_t)row * (D / 4));
        }
        #pragma unroll
        for (int k = 0; k < 8; ++k) {
            const int s = __shfl_sync(0xffffffffu, myseg, jb * 8 + k);
            if (s != cur) {                  // warp-uniform branch
                float* o = out + (size_t)cur * (F * D) + f * D + lane * 4;
                atomicAdd(o + 0, acc.x);
                atomicAdd(o + 1, acc.y);
                atomicAdd(o + 2, acc.z);
                atomicAdd(o + 3, acc.w);
                acc = make_float4(0.f, 0.f, 0.f, 0.f);
                cur = s;
            }
            acc.x += v[k].x; acc.y += v[k].y; acc.z += v[k].z; acc.w += v[k].w;
        }
    }
    // final flush
    float* o = out + (size_t)cur * (F * D) + f * D + lane * 4;
    atomicAdd(o + 0, acc.x);
    atomicAdd(o + 1, acc.y);
    atomicAdd(o + 2, acc.z);
    atomicAdd(o + 3, acc.w);
}

extern "C" void kernel_launch(void* const* d_in, const int* in_sizes, int n_in,
                              void* d_out, int out_size)
{
    const int*   values  = (const int*)d_in[0];   // [F, NVALS] int32
    const int*   offsets = (const int*)d_in[1];   // [F, B+1] int32
    const float* tables  = (const float*)d_in[2]; // [F, V, D] float32
    float*       out     = (float*)d_out;         // [B, F*D] float32

    // 1) zero the output (atomics accumulate into it)
    const int n4 = (B * F * D) / 4;                // 1,048,576 float4
    zero_out_kernel<<<(n4 + 255) / 256, 256>>>((float4*)out, n4);

    // 2) balanced gather + segment-reduce
    const int total_warps = F * CPF;               // 20480
    const int threads = 256;                       // 8 warps/block
    const int blocks = (total_warps * 32) / threads;  // 2560
    ebc_chunk_kernel<<<blocks, threads>>>(values, offsets, tables, out);
}

// round 4
// speedup vs baseline: 1.6172x; 1.0251x over previous
#include <cuda_runtime.h>
#include <cstdint>

// Problem constants (from reference)
#define F 8
#define B 4096
#define V 100000
#define D 128
#define NVALS 81920
#define CHUNK 32
#define CPF (NVALS / CHUNK)   // 2560 chunks per feature

// Scratch: precomputed bag id for every jagged value (2.6 MB)
__device__ int g_seg[F * NVALS];

__global__ __launch_bounds__(256)
void zero_out_kernel(float4* __restrict__ out, int n4)
{
    int i = blockIdx.x * blockDim.x + threadIdx.x;
    if (i < n4) out[i] = make_float4(0.f, 0.f, 0.f, 0.f);
}

// seg[f][pos] = searchsorted(offs_f, pos, right) - 1. One thread per value;
// 12-step binary search over the L1/L2-resident 16KB offsets array.
__global__ __launch_bounds__(256)
void seg_kernel(const int* __restrict__ offsets)   // [F, B+1]
{
    const int id = blockIdx.x * blockDim.x + threadIdx.x;
    if (id >= F * NVALS) return;
    const int f   = id / NVALS;
    const int pos = id - f * NVALS;
    const int* offs = offsets + f * (B + 1);
    int lo = 0, hi = B - 1;
    #pragma unroll
    for (int it = 0; it < 12; ++it) {     // 2^12 = 4096 covers [0, B-1]
        int mid = (lo + hi + 1) >> 1;
        if (__ldg(offs + mid) <= pos) lo = mid; else hi = mid - 1;
    }
    g_seg[id] = lo;
}

// One warp per 32-value chunk (perfectly balanced). Lane l owns float4 slice
// [4l, 4l+4) of D=128. 8 row-gathers staged in flight (MLP=8). Partial bag
// sums flushed with one red.global.add.v4.f32 per lane.
__global__ __launch_bounds__(256, 5)
void ebc_chunk_kernel(const int* __restrict__ values,    // [F, NVALS]
                      const float* __restrict__ tables,  // [F, V, D]
                      float* __restrict__ out)           // [B, F*D]
{
    const int gwarp = (blockIdx.x * blockDim.x + threadIdx.x) >> 5;
    const int lane  = threadIdx.x & 31;

    // f-major: consecutive warps share a table (L2 locality)
    const int f = gwarp / CPF;
    const int c = gwarp - f * CPF;
    const int pos = c * CHUNK + lane;        // this lane's value position

    const int myidx = __ldg(values + (size_t)f * NVALS + pos);
    const int myseg = g_seg[(size_t)f * NVALS + pos];

    const float4* tab = reinterpret_cast<const float4*>(tables)
                        + (size_t)f * V * (D / 4) + lane;

    float4 acc = make_float4(0.f, 0.f, 0.f, 0.f);
    int cur = __shfl_sync(0xffffffffu, myseg, 0);

    #pragma unroll
    for (int jb = 0; jb < CHUNK / 8; ++jb) {
        // Stage 8 independent warp-wide row gathers (true MLP=8)
        float4 v[8];
        #pragma unroll
        for (int k = 0; k < 8; ++k) {
            const int row = __shfl_sync(0xffffffffu, myidx, jb * 8 + k);
            v[k] = __ldcg(tab + (size_t)row * (D / 4));
        }
        #pragma unroll
        for (int k = 0; k < 8; ++k) {
            const int s = __shfl_sync(0xffffffffu, myseg, jb * 8 + k);
            if (s != cur) {                  // warp-uniform branch
                float* o = out + (size_t)cur * (F * D) + f * D + lane * 4;
                asm volatile("red.global.add.v4.f32 [%0], {%1,%2,%3,%4};"
                             :: "l"(o), "f"(acc.x), "f"(acc.y), "f"(acc.z), "f"(acc.w)
                             : "memory");
                acc = make_float4(0.f, 0.f, 0.f, 0.f);
                cur = s;
            }
            acc.x += v[k].x; acc.y += v[k].y; acc.z += v[k].z; acc.w += v[k].w;
        }
    }
    // final flush
    float* o = out + (size_t)cur * (F * D) + f * D + lane * 4;
    asm volatile("red.global.add.v4.f32 [%0], {%1,%2,%3,%4};"
                 :: "l"(o), "f"(acc.x), "f"(acc.y), "f"(acc.z), "f"(acc.w)
                 : "memory");
}

extern "C" void kernel_launch(void* const* d_in, const int* in_sizes, int n_in,
                              void* d_out, int out_size)
{
    const int*   values  = (const int*)d_in[0];   // [F, NVALS] int32
    const int*   offsets = (const int*)d_in[1];   // [F, B+1] int32
    const float* tables  = (const float*)d_in[2]; // [F, V, D] float32
    float*       out     = (float*)d_out;         // [B, F*D] float32

    // 1) zero the output (atomics accumulate into it)
    const int n4 = (B * F * D) / 4;                // 1,048,576 float4
    zero_out_kernel<<<(n4 + 255) / 256, 256>>>((float4*)out, n4);

    // 2) precompute bag ids for all values
    seg_kernel<<<(F * NVALS + 255) / 256, 256>>>(offsets);

    // 3) balanced gather + segment-reduce
    const int total_warps = F * CPF;               // 20480
    const int threads = 256;                       // 8 warps/block
    const int blocks = (total_warps * 32) / threads;  // 2560
    ebc_chunk_kernel<<<blocks, threads>>>(values, tables, out);
}

// round 5
// speedup vs baseline: 1.6893x; 1.0446x over previous
#include <cuda_runtime.h>
#include <cstdint>

// Problem constants (from reference)
#define F 8
#define B 4096
#define V 100000
#define D 128
#define NVALS 81920
#define CHUNK 32
#define CPF (NVALS / CHUNK)   // 2560 chunks per feature

// Scratch: precomputed bag id for every jagged value (2.6 MB)
__device__ int g_seg[F * NVALS];

// Fused init: zero the output AND compute seg ids, one launch.
// Grid: 2560 blocks x 256 = 655,360 threads (= F*NVALS).
__global__ __launch_bounds__(256)
void init_kernel(const int* __restrict__ offsets,   // [F, B+1]
                 float4* __restrict__ out4)         // [B*F*D/4]
{
    const int id = blockIdx.x * blockDim.x + threadIdx.x;
    const int NT = F * NVALS;                       // 655,360

    // (a) zero output: 1,048,576 float4, grid-stride (1-2 per thread)
    for (int i = id; i < (B * F * D) / 4; i += NT)
        out4[i] = make_float4(0.f, 0.f, 0.f, 0.f);

    // (b) seg[f][pos] = searchsorted(offs_f, pos, right) - 1
    const int f   = id / NVALS;
    const int pos = id - f * NVALS;
    const int* offs = offsets + f * (B + 1);
    int lo = 0, hi = B - 1;
    #pragma unroll
    for (int it = 0; it < 12; ++it) {               // 2^12 = 4096 covers [0, B-1]
        int mid = (lo + hi + 1) >> 1;
        if (__ldg(offs + mid) <= pos) lo = mid; else hi = mid - 1;
    }
    g_seg[id] = lo;
}

// One warp per 32-value chunk (perfectly balanced). Lane l owns float4 slice
// [4l, 4l+4) of D=128. Software-pipelined: batch jb+1's 8 row gathers are
// issued before batch jb is consumed -> near-continuous load issue per warp.
__global__ __launch_bounds__(128, 6)
void ebc_chunk_kernel(const int* __restrict__ values,    // [F, NVALS]
                      const float* __restrict__ tables,  // [F, V, D]
                      float* __restrict__ out)           // [B, F*D]
{
    const int gwarp = (blockIdx.x * blockDim.x + threadIdx.x) >> 5;
    const int lane  = threadIdx.x & 31;

    // f-major: consecutive warps share a table (L2 locality)
    const int f = gwarp / CPF;
    const int c = gwarp - f * CPF;
    const int pos = c * CHUNK + lane;        // this lane's value position

    const int myidx = __ldg(values + (size_t)f * NVALS + pos);
    const int myseg = g_seg[(size_t)f * NVALS + pos];

    const float4* tab = reinterpret_cast<const float4*>(tables)
                        + (size_t)f * V * (D / 4) + lane;

    float4 v[2][8];

    // prologue: issue batch 0
    #pragma unroll
    for (int k = 0; k < 8; ++k) {
        const int row = __shfl_sync(0xffffffffu, myidx, k);
        v[0][k] = __ldcg(tab + (size_t)row * (D / 4));
    }

    float4 acc = make_float4(0.f, 0.f, 0.f, 0.f);
    int cur = __shfl_sync(0xffffffffu, myseg, 0);

    #pragma unroll
    for (int jb = 0; jb < CHUNK / 8; ++jb) {
        const int buf = jb & 1;
        // prefetch next batch before consuming current
        if (jb + 1 < CHUNK / 8) {
            #pragma unroll
            for (int k = 0; k < 8; ++k) {
                const int row = __shfl_sync(0xffffffffu, myidx, (jb + 1) * 8 + k);
                v[buf ^ 1][k] = __ldcg(tab + (size_t)row * (D / 4));
            }
        }
        // consume current batch
        #pragma unroll
        for (int k = 0; k < 8; ++k) {
            const int s = __shfl_sync(0xffffffffu, myseg, jb * 8 + k);
            if (s != cur) {                  // warp-uniform branch
                float* o = out + (size_t)cur * (F * D) + f * D + lane * 4;
                asm volatile("red.global.add.v4.f32 [%0], {%1,%2,%3,%4};"
                             :: "l"(o), "f"(acc.x), "f"(acc.y), "f"(acc.z), "f"(acc.w)
                             : "memory");
                acc = make_float4(0.f, 0.f, 0.f, 0.f);
                cur = s;
            }
            acc.x += v[buf][k].x; acc.y += v[buf][k].y;
            acc.z += v[buf][k].z; acc.w += v[buf][k].w;
        }
    }
    // final flush
    float* o = out + (size_t)cur * (F * D) + f * D + lane * 4;
    asm volatile("red.global.add.v4.f32 [%0], {%1,%2,%3,%4};"
                 :: "l"(o), "f"(acc.x), "f"(acc.y), "f"(acc.z), "f"(acc.w)
                 : "memory");
}

extern "C" void kernel_launch(void* const* d_in, const int* in_sizes, int n_in,
                              void* d_out, int out_size)
{
    const int*   values  = (const int*)d_in[0];   // [F, NVALS] int32
    const int*   offsets = (const int*)d_in[1];   // [F, B+1] int32
    const float* tables  = (const float*)d_in[2]; // [F, V, D] float32
    float*       out     = (float*)d_out;         // [B, F*D] float32

    // 1) fused zero-output + seg precompute
    init_kernel<<<(F * NVALS) / 256, 256>>>(offsets, (float4*)out);

    // 2) balanced, pipelined gather + segment-reduce
    const int total_warps = F * CPF;               // 20480
    const int threads = 128;                       // 4 warps/block
    const int blocks = (total_warps * 32) / threads;  // 5120
    ebc_chunk_kernel<<<blocks, threads>>>(values, tables, out);
}